// round 5
// baseline (speedup 1.0000x reference)
#include <cuda_runtime.h>
#include <math.h>
#include <stdint.h>

// ---------------- problem constants ----------------
#define CDIM   192
#define HEADS  8
#define HD     24
#define NTOK   64
#define BATCH  4
#define HIMG   256
#define WIMG   256
#define NWX    32          // windows per image row
#define NW     1024        // windows per image
#define BWIN   4096        // total windows
#define TPIX   262144      // total tokens / pixels
#define CMID   768
#define QSCALE 0.20412414523193154f   // 24^-0.5
#define LN_EPS 1e-5f

#define LN_SMEM_BYTES ((CDIM*128 + 2*CDIM)*4)

// ---------------- scratch (static device arrays; no runtime allocation) ----------------
__device__ float g_hwin[(size_t)TPIX*CDIM];
__device__ float g_q[(size_t)BWIN*HEADS*NTOK*HD];
__device__ float g_k[(size_t)BWIN*HEADS*NTOK*HD];
__device__ float g_v[(size_t)BWIN*HEADS*NTOK*HD];
__device__ float g_att[(size_t)TPIX*CDIM];
__device__ float g_proj[(size_t)TPIX*CDIM];
__device__ float g_xh[(size_t)TPIX*CDIM];
__device__ float g_h2[(size_t)TPIX*CDIM];
__device__ float g_mid[(size_t)TPIX*CMID];
__device__ float g_y[(size_t)TPIX*CDIM];

// ============ kernel 1: LN1 + roll(-4,-4) + window partition ============
__global__ void __launch_bounds__(128) ln1_partition_kernel(
    const float* __restrict__ x, const float* __restrict__ g, const float* __restrict__ b)
{
    extern __shared__ float s[];
    float* sg = s + CDIM*128;
    float* sb = sg + CDIM;
    const int tid = threadIdx.x;
    const int w0 = blockIdx.x*128, h = blockIdx.y, bb = blockIdx.z;
    for (int i = tid; i < CDIM; i += 128){ sg[i]=g[i]; sb[i]=b[i]; }
    const float* xp = x + (size_t)bb*CDIM*HIMG*WIMG + (size_t)h*WIMG + w0;
    #pragma unroll 4
    for (int c=0;c<CDIM;c++) s[c*128+tid] = xp[(size_t)c*(HIMG*WIMG)+tid];
    __syncthreads();
    float sum=0.f, sq=0.f;
    for (int c=0;c<CDIM;c++){ float v=s[c*128+tid]; sum+=v; sq+=v*v; }
    const float mean = sum*(1.f/CDIM);
    const float var  = sq*(1.f/CDIM) - mean*mean;
    const float rstd = rsqrtf(var + LN_EPS);
    const int w  = w0 + tid;
    const int hr = (h-4)&255, wr = (w-4)&255;      // position in shifted map
    const int win = bb*NW + (hr>>3)*NWX + (wr>>3);
    const size_t base = ((size_t)win*NTOK + ((hr&7)<<3) + (wr&7))*CDIM;
    for (int c=0;c<CDIM;c++)
        g_hwin[base+c] = (s[c*128+tid]-mean)*rstd*sg[c] + sb[c];
}

// ============ FFMA2 SGEMM: C = A(MxK) @ B(KxN) + bias, fused epilogue ============
// BM=128, BN=96, BK=16, 256 threads, per-thread 8 rows x 6 cols (3 f32x2 pairs).
#define BM 128
#define BN 96
#define BK 16

// EPI: 0 = qkv split (+q scale), 1 = plain, 2 = exact GELU, 3 = residual add
template<int EPI>
__global__ void __launch_bounds__(256) gemm_kernel(
    const float* __restrict__ A, const float* __restrict__ Bw,
    const float* __restrict__ bias,
    float* __restrict__ o0, float* __restrict__ o1, float* __restrict__ o2,
    const float* __restrict__ res, int K, int Ncols)
{
    __shared__ __align__(16) float AsD[BK][2*BM+2];   // A duplicated pairwise
    __shared__ __align__(16) float Bs [BK][BN];
    const int tid = threadIdx.x;
    const int tx = tid & 15;     // N direction: 6 cols
    const int ty = tid >> 4;     // M direction: 8 rows
    const int m0 = blockIdx.y * BM;
    const int n0 = blockIdx.x * BN;

    unsigned long long acc[8][3];
    #pragma unroll
    for (int i=0;i<8;i++){ acc[i][0]=0ull; acc[i][1]=0ull; acc[i][2]=0ull; }

    for (int k0=0;k0<K;k0+=BK){
        #pragma unroll
        for (int j=0;j<8;j++){
            int r = tid + j*256;
            int mm = r >> 4, kk = r & 15;
            float v = A[(size_t)(m0+mm)*K + (k0+kk)];
            float2 d = make_float2(v, v);
            *reinterpret_cast<float2*>(&AsD[kk][2*mm]) = d;
        }
        #pragma unroll
        for (int j=0;j<6;j++){
            int r = tid + j*256;
            int kk = r / BN, nn = r - kk*BN;
            Bs[kk][nn] = Bw[(size_t)(k0+kk)*Ncols + n0 + nn];
        }
        __syncthreads();
        #pragma unroll
        for (int k=0;k<BK;k++){
            unsigned long long bp[3];
            #pragma unroll
            for (int jj=0;jj<3;jj++)
                bp[jj] = *reinterpret_cast<const unsigned long long*>(&Bs[k][tx*6 + jj*2]);
            #pragma unroll
            for (int i=0;i<8;i++){
                const unsigned long long a2 =
                    *reinterpret_cast<const unsigned long long*>(&AsD[k][(ty*8+i)*2]);
                asm("fma.rn.f32x2 %0, %1, %2, %0;" : "+l"(acc[i][0]) : "l"(a2), "l"(bp[0]));
                asm("fma.rn.f32x2 %0, %1, %2, %0;" : "+l"(acc[i][1]) : "l"(a2), "l"(bp[1]));
                asm("fma.rn.f32x2 %0, %1, %2, %0;" : "+l"(acc[i][2]) : "l"(a2), "l"(bp[2]));
            }
        }
        __syncthreads();
    }

    #pragma unroll
    for (int i=0;i<8;i++){
        const int row = m0 + ty*8 + i;
        #pragma unroll
        for (int jj=0;jj<3;jj++){
            float vx, vy;
            asm("mov.b64 {%0,%1}, %2;" : "=f"(vx), "=f"(vy) : "l"(acc[i][jj]));
            float vals[2] = {vx, vy};
            #pragma unroll
            for (int e=0;e<2;e++){
                const int col = n0 + tx*6 + jj*2 + e;
                float v = vals[e] + bias[col];
                if (EPI == 0){
                    const int qi   = col / CDIM;
                    const int rem  = col - qi*CDIM;
                    const int head = rem / HD, hd = rem - head*HD;
                    const int win  = row >> 6, tok = row & 63;
                    const size_t dst = (((size_t)win*HEADS + head)*NTOK + tok)*HD + hd;
                    if (qi==0)      o0[dst] = v*QSCALE;
                    else if (qi==1) o1[dst] = v;
                    else            o2[dst] = v;
                } else if (EPI == 1){
                    o0[(size_t)row*Ncols + col] = v;
                } else if (EPI == 2){
                    o0[(size_t)row*Ncols + col] =
                        0.5f*v*(1.f + erff(v*0.70710678118654752f));
                } else {
                    const size_t idx = (size_t)row*Ncols + col;
                    o0[idx] = res[idx] + v;
                }
            }
        }
    }
}

// ============ kernel 3: windowed attention, one block per (window, head) ============
__global__ void __launch_bounds__(64) attn_kernel(const float* __restrict__ rpb)
{
    __shared__ float sk[NTOK*HD];
    __shared__ float sv[NTOK*HD];
    __shared__ float srp[225];
    __shared__ float Ss[NTOK*64];
    const int blk = blockIdx.x;        // win*8 + head
    const int win = blk >> 3, head = blk & 7;
    const int tid = threadIdx.x;       // query token
    const size_t base = (size_t)blk * (NTOK*HD);
    for (int i=tid;i<NTOK*HD;i+=64){ sk[i]=g_k[base+i]; sv[i]=g_v[base+i]; }
    for (int i=tid;i<225;i+=64) srp[i] = rpb[(size_t)i*HEADS + head];

    float qreg[24];
    {
        const float4* qp = reinterpret_cast<const float4*>(&g_q[base + (size_t)tid*HD]);
        #pragma unroll
        for (int i=0;i<6;i++){
            float4 t = qp[i];
            qreg[4*i]=t.x; qreg[4*i+1]=t.y; qreg[4*i+2]=t.z; qreg[4*i+3]=t.w;
        }
    }
    __syncthreads();

    const int wrow = (win & (NW-1)) >> 5;
    const int wcol = win & 31;
    const int r1 = tid >> 3, c1 = tid & 7;

    float mx = -1e30f;
    #pragma unroll 4
    for (int m=0;m<NTOK;m++){
        float s = 0.f;
        #pragma unroll
        for (int d=0;d<24;d++) s += qreg[d]*sk[m*24+d];
        const int r2 = m>>3, c2 = m&7;
        s += srp[(r1-r2+7)*15 + (c1-c2+7)];
        const bool masked = (wrow==31 && ((r1>>2)!=(r2>>2))) ||
                            (wcol==31 && ((c1>>2)!=(c2>>2)));
        if (masked) s -= 100.f;
        Ss[m*64+tid] = s;
        mx = fmaxf(mx, s);
    }
    float sum = 0.f;
    #pragma unroll 4
    for (int m=0;m<NTOK;m++){
        float e = __expf(Ss[m*64+tid] - mx);
        Ss[m*64+tid] = e;
        sum += e;
    }
    const float inv = 1.f/sum;
    float o[24];
    #pragma unroll
    for (int d=0;d<24;d++) o[d]=0.f;
    #pragma unroll 4
    for (int m=0;m<NTOK;m++){
        const float p = Ss[m*64+tid]*inv;
        #pragma unroll
        for (int d=0;d<24;d++) o[d] += p*sv[m*24+d];
    }
    float* op = &g_att[((size_t)win*NTOK + tid)*CDIM + head*HD];
    #pragma unroll
    for (int i=0;i<6;i++)
        reinterpret_cast<float4*>(op)[i] = make_float4(o[4*i],o[4*i+1],o[4*i+2],o[4*i+3]);
}

// ============ kernel 5: window reverse + roll(+4,+4) + residual + LN2 ============
__global__ void __launch_bounds__(128) postattn_kernel(
    const float* __restrict__ x, const float* __restrict__ g, const float* __restrict__ b)
{
    extern __shared__ float s[];
    float* sg = s + CDIM*128;
    float* sb = sg + CDIM;
    const int tid = threadIdx.x;
    const int w0 = blockIdx.x*128, h = blockIdx.y, bb = blockIdx.z;
    for (int i=tid;i<CDIM;i+=128){ sg[i]=g[i]; sb[i]=b[i]; }
    const float* xp = x + (size_t)bb*CDIM*HIMG*WIMG + (size_t)h*WIMG + w0;
    #pragma unroll 4
    for (int c=0;c<CDIM;c++) s[c*128+tid] = xp[(size_t)c*(HIMG*WIMG)+tid];
    __syncthreads();
    const int w  = w0 + tid;
    const int hr = (h-4)&255, wr = (w-4)&255;
    const int win = bb*NW + (hr>>3)*NWX + (wr>>3);
    const size_t pbase = ((size_t)win*NTOK + ((hr&7)<<3) + (wr&7))*CDIM;
    float sum=0.f, sq=0.f;
    for (int c=0;c<CDIM;c++){
        float v = s[c*128+tid] + g_proj[pbase+c];
        s[c*128+tid] = v; sum += v; sq += v*v;
    }
    const float mean = sum*(1.f/CDIM);
    const float var  = sq*(1.f/CDIM) - mean*mean;
    const float rstd = rsqrtf(var + LN_EPS);
    const size_t ob = (((size_t)bb*HIMG + h)*WIMG + w)*CDIM;
    for (int c=0;c<CDIM;c++){
        float v = s[c*128+tid];
        g_xh[ob+c] = v;
        g_h2[ob+c] = (v-mean)*rstd*sg[c] + sb[c];
    }
}

// ============ kernel 8: BHWC -> BCHW output transpose ============
__global__ void out_transpose_kernel(float* __restrict__ out)
{
    __shared__ float t[32][33];
    const int tx = threadIdx.x, ty = threadIdx.y;   // (32, 8)
    const int w0 = blockIdx.x*32, h = blockIdx.y, bb = blockIdx.z;
    const size_t trow = ((size_t)bb*HIMG + h)*WIMG + w0;
    for (int c0=0;c0<CDIM;c0+=32){
        #pragma unroll
        for (int j=0;j<4;j++){
            int wl = ty + j*8;
            t[wl][tx] = g_y[(trow+wl)*CDIM + c0 + tx];
        }
        __syncthreads();
        #pragma unroll
        for (int j=0;j<4;j++){
            int cl = ty + j*8;
            out[(((size_t)bb*CDIM + c0+cl)*HIMG + h)*WIMG + w0 + tx] = t[tx][cl];
        }
        __syncthreads();
    }
}

// ============ launch ============
extern "C" void kernel_launch(void* const* d_in, const int* in_sizes, int n_in,
                              void* d_out, int out_size)
{
    (void)in_sizes; (void)n_in; (void)out_size;
    const float* x      = (const float*)d_in[0];
    const float* n1g    = (const float*)d_in[1];
    const float* n1b    = (const float*)d_in[2];
    const float* qkv_w  = (const float*)d_in[3];
    const float* qkv_b  = (const float*)d_in[4];
    const float* proj_w = (const float*)d_in[5];
    const float* proj_b = (const float*)d_in[6];
    const float* rpb    = (const float*)d_in[7];
    const float* n2g    = (const float*)d_in[8];
    const float* n2b    = (const float*)d_in[9];
    const float* fc1_w  = (const float*)d_in[10];
    const float* fc1_b  = (const float*)d_in[11];
    const float* fc2_w  = (const float*)d_in[12];
    const float* fc2_b  = (const float*)d_in[13];
    float* out = (float*)d_out;

    float *hwin,*q,*k,*v,*att,*proj,*xh,*h2,*mid,*y;
    cudaGetSymbolAddress((void**)&hwin, g_hwin);
    cudaGetSymbolAddress((void**)&q,    g_q);
    cudaGetSymbolAddress((void**)&k,    g_k);
    cudaGetSymbolAddress((void**)&v,    g_v);
    cudaGetSymbolAddress((void**)&att,  g_att);
    cudaGetSymbolAddress((void**)&proj, g_proj);
    cudaGetSymbolAddress((void**)&xh,   g_xh);
    cudaGetSymbolAddress((void**)&h2,   g_h2);
    cudaGetSymbolAddress((void**)&mid,  g_mid);
    cudaGetSymbolAddress((void**)&y,    g_y);

    static bool attr_done = false;
    if (!attr_done){
        cudaFuncSetAttribute(ln1_partition_kernel,
            cudaFuncAttributeMaxDynamicSharedMemorySize, LN_SMEM_BYTES);
        cudaFuncSetAttribute(postattn_kernel,
            cudaFuncAttributeMaxDynamicSharedMemorySize, LN_SMEM_BYTES);
        attr_done = true;
    }

    const dim3 lnGrid(WIMG/128, HIMG, BATCH);

    // 1. LN1 + roll + window partition
    ln1_partition_kernel<<<lnGrid, 128, LN_SMEM_BYTES>>>(x, n1g, n1b);

    // 2. qkv GEMM (262144 x 192) @ (192 x 576), split q/k/v, q pre-scaled
    gemm_kernel<0><<<dim3(576/BN, TPIX/BM), 256>>>(
        hwin, qkv_w, qkv_b, q, k, v, nullptr, CDIM, 3*CDIM);

    // 3. attention per (window, head)
    attn_kernel<<<BWIN*HEADS, 64>>>(rpb);

    // 4. proj GEMM (262144 x 192) @ (192 x 192)
    gemm_kernel<1><<<dim3(CDIM/BN, TPIX/BM), 256>>>(
        att, proj_w, proj_b, proj, nullptr, nullptr, nullptr, CDIM, CDIM);

    // 5. window reverse + roll + residual + LN2
    postattn_kernel<<<lnGrid, 128, LN_SMEM_BYTES>>>(x, n2g, n2b);

    // 6. fc1 GEMM (262144 x 192) @ (192 x 768) + GELU
    gemm_kernel<2><<<dim3(CMID/BN, TPIX/BM), 256>>>(
        h2, fc1_w, fc1_b, mid, nullptr, nullptr, nullptr, CDIM, CMID);

    // 7. fc2 GEMM (262144 x 768) @ (768 x 192) + residual
    gemm_kernel<3><<<dim3(CDIM/BN, TPIX/BM), 256>>>(
        mid, fc2_w, fc2_b, y, nullptr, nullptr, xh, CMID, CDIM);

    // 8. BHWC -> BCHW
    out_transpose_kernel<<<dim3(WIMG/32, HIMG, BATCH), dim3(32,8)>>>(out);
}

// round 7
// speedup vs baseline: 1.4726x; 1.4726x over previous
#include <cuda_runtime.h>
#include <cuda_bf16.h>
#include <math.h>
#include <stdint.h>

// ---------------- problem constants ----------------
#define CDIM   192
#define HEADS  8
#define HD     24
#define NTOK   64
#define BATCH  4
#define HIMG   256
#define WIMG   256
#define NWX    32
#define NW     1024
#define BWIN   4096
#define TPIX   262144
#define CMID   768
#define QSCALE 0.20412414523193154f
#define LN_EPS 1e-5f

#define LN_SMEM_BYTES ((CDIM*128 + 2*CDIM)*4)

// ---------------- scratch ----------------
__device__ float g_hwin[(size_t)TPIX*CDIM];
__device__ float g_q[(size_t)BWIN*HEADS*NTOK*HD];
__device__ float g_k[(size_t)BWIN*HEADS*NTOK*HD];
__device__ float g_v[(size_t)BWIN*HEADS*NTOK*HD];
__device__ float g_att[(size_t)TPIX*CDIM];
__device__ float g_proj[(size_t)TPIX*CDIM];
__device__ float g_xh[(size_t)TPIX*CDIM];
__device__ float g_h2[(size_t)TPIX*CDIM];
__device__ float g_mid[(size_t)TPIX*CMID];
__device__ float g_y[(size_t)TPIX*CDIM];

// ---------------- helpers ----------------
__device__ __forceinline__ uint32_t smem_u32(const void* p){
    uint32_t a;
    asm("{ .reg .u64 t; cvta.to.shared.u64 t, %1; cvt.u32.u64 %0, t; }" : "=r"(a) : "l"(p));
    return a;
}

__device__ __forceinline__ void ldsm_x4(uint32_t* r, uint32_t addr){
    asm volatile("ldmatrix.sync.aligned.m8n8.x4.shared.b16 {%0,%1,%2,%3}, [%4];"
        : "=r"(r[0]), "=r"(r[1]), "=r"(r[2]), "=r"(r[3]) : "r"(addr));
}

__device__ __forceinline__ void mma16816(float* d, const uint32_t* a,
                                         uint32_t b0, uint32_t b1){
    asm volatile("mma.sync.aligned.m16n8k16.row.col.f32.bf16.bf16.f32 "
        "{%0,%1,%2,%3}, {%4,%5,%6,%7}, {%8,%9}, {%0,%1,%2,%3};"
        : "+f"(d[0]), "+f"(d[1]), "+f"(d[2]), "+f"(d[3])
        : "r"(a[0]), "r"(a[1]), "r"(a[2]), "r"(a[3]), "r"(b0), "r"(b1));
}

// ============ kernel 1: LN1 + roll(-4,-4) + window partition ============
__global__ void __launch_bounds__(128) ln1_partition_kernel(
    const float* __restrict__ x, const float* __restrict__ g, const float* __restrict__ b)
{
    extern __shared__ float s[];
    float* sg = s + CDIM*128;
    float* sb = sg + CDIM;
    const int tid = threadIdx.x;
    const int w0 = blockIdx.x*128, h = blockIdx.y, bb = blockIdx.z;
    for (int i = tid; i < CDIM; i += 128){ sg[i]=g[i]; sb[i]=b[i]; }
    const float* xp = x + (size_t)bb*CDIM*HIMG*WIMG + (size_t)h*WIMG + w0;
    #pragma unroll 4
    for (int c=0;c<CDIM;c++) s[c*128+tid] = xp[(size_t)c*(HIMG*WIMG)+tid];
    __syncthreads();
    float sum=0.f, sq=0.f;
    for (int c=0;c<CDIM;c++){ float v=s[c*128+tid]; sum+=v; sq+=v*v; }
    const float mean = sum*(1.f/CDIM);
    const float var  = sq*(1.f/CDIM) - mean*mean;
    const float rstd = rsqrtf(var + LN_EPS);
    const int w  = w0 + tid;
    const int hr = (h-4)&255, wr = (w-4)&255;
    const int win = bb*NW + (hr>>3)*NWX + (wr>>3);
    const size_t base = ((size_t)win*NTOK + ((hr&7)<<3) + (wr&7))*CDIM;
    for (int c=0;c<CDIM;c++)
        g_hwin[base+c] = (s[c*128+tid]-mean)*rstd*sg[c] + sb[c];
}

// ============ HMMA bf16 hi/lo GEMM: C = A(MxK) @ B(KxN) + bias, fused epilogue ============
// Block tile 128x64, BK=64, 8 warps (4x2), warp tile 32x32, 3-pass hi/lo bf16.
#define GPAD 72                              // padded row length (bf16 elems)
#define SM_AHI 0
#define SM_ALO (128*GPAD*2)                  // 18432 B
#define SM_BHI (2*128*GPAD*2)                // 36864 B
#define SM_BLO (SM_BHI + 64*GPAD*2)          // 46080 B
#define SMEM_MMA (SM_BLO + 64*GPAD*2)        // 55296 B

// EPI: 0 = qkv split (+q scale), 1 = plain, 2 = exact GELU, 3 = residual add
template<int EPI>
__global__ void __launch_bounds__(256,2) mma_gemm(
    const float* __restrict__ A, const float* __restrict__ Bw,
    const float* __restrict__ bias,
    float* __restrict__ o0, float* __restrict__ o1, float* __restrict__ o2,
    const float* __restrict__ res, int K, int Ncols)
{
    extern __shared__ __align__(16) char dsm[];
    __nv_bfloat16* sAhi = reinterpret_cast<__nv_bfloat16*>(dsm + SM_AHI);
    __nv_bfloat16* sAlo = reinterpret_cast<__nv_bfloat16*>(dsm + SM_ALO);
    __nv_bfloat16* sBhi = reinterpret_cast<__nv_bfloat16*>(dsm + SM_BHI);
    __nv_bfloat16* sBlo = reinterpret_cast<__nv_bfloat16*>(dsm + SM_BLO);
    const uint32_t sbase = smem_u32(dsm);

    const int tid = threadIdx.x;
    const int wid = tid >> 5, lane = tid & 31;
    const int wm = wid >> 1, wn = wid & 1;          // 4 x 2 warp grid
    const int m0 = blockIdx.y * 128;
    const int n0 = blockIdx.x * 64;

    float acc[2][4][4];
    #pragma unroll
    for (int mi=0;mi<2;mi++)
        #pragma unroll
        for (int nj=0;nj<4;nj++)
            #pragma unroll
            for (int e=0;e<4;e++) acc[mi][nj][e]=0.f;

    // ldmatrix lane-address components (x4 pattern)
    const int off16 = lane & 15;
    const int hi8   = (lane >> 4) * 8;

    uint32_t aAddr[2], bAddr[2];
    #pragma unroll
    for (int mi=0;mi<2;mi++)
        aAddr[mi] = sbase + (uint32_t)(((wm*32 + mi*16 + off16)*GPAD + hi8)*2);
    #pragma unroll
    for (int nj2=0;nj2<2;nj2++)
        bAddr[nj2] = sbase + SM_BHI + (uint32_t)(((wn*32 + nj2*16 + off16)*GPAD + hi8)*2);

    for (int k0=0; k0<K; k0+=64){
        // ---- stage A chunk: 128 rows x 64 k, fp32 -> bf16 hi/lo ----
        #pragma unroll
        for (int it = tid; it < 128*32; it += 256){
            const int row = it >> 5, kp = it & 31;
            const float2 v = *reinterpret_cast<const float2*>(
                &A[(size_t)(m0+row)*K + k0 + kp*2]);
            __nv_bfloat16 hx = __float2bfloat16_rn(v.x);
            __nv_bfloat16 hy = __float2bfloat16_rn(v.y);
            __nv_bfloat16 lx = __float2bfloat16_rn(v.x - __bfloat162float(hx));
            __nv_bfloat16 ly = __float2bfloat16_rn(v.y - __bfloat162float(hy));
            const int o = row*GPAD + kp*2;
            *reinterpret_cast<__nv_bfloat162*>(&sAhi[o]) = __nv_bfloat162(hx, hy);
            *reinterpret_cast<__nv_bfloat162*>(&sAlo[o]) = __nv_bfloat162(lx, ly);
        }
        // ---- stage B chunk: [K][N] global -> [n][k] smem, hi/lo ----
        #pragma unroll
        for (int it = tid; it < 64*64; it += 256){
            const int nn = it & 63, kk = it >> 6;
            const float v = Bw[(size_t)(k0+kk)*Ncols + n0 + nn];
            __nv_bfloat16 h = __float2bfloat16_rn(v);
            __nv_bfloat16 l = __float2bfloat16_rn(v - __bfloat162float(h));
            const int o = nn*GPAD + kk;
            sBhi[o] = h;
            sBlo[o] = l;
        }
        __syncthreads();

        // ---- 4 k16 steps ----
        #pragma unroll
        for (int kk=0; kk<4; kk++){
            const uint32_t kb = (uint32_t)(kk*32);   // 16 bf16 = 32 bytes
            uint32_t ah[2][4], al[2][4];
            #pragma unroll
            for (int mi=0;mi<2;mi++){
                ldsm_x4(ah[mi], aAddr[mi] + kb);
                ldsm_x4(al[mi], aAddr[mi] + SM_ALO + kb);
            }
            #pragma unroll
            for (int nj2=0;nj2<2;nj2++){
                uint32_t bh[4], bl[4];
                ldsm_x4(bh, bAddr[nj2] + kb);
                ldsm_x4(bl, bAddr[nj2] + (SM_BLO - SM_BHI) + kb);
                #pragma unroll
                for (int mi=0;mi<2;mi++){
                    #pragma unroll
                    for (int njl=0;njl<2;njl++){
                        float* d = acc[mi][nj2*2+njl];
                        mma16816(d, ah[mi], bh[njl], bh[njl+2]);   // ah*bh
                        mma16816(d, ah[mi], bl[njl], bl[njl+2]);   // ah*bl
                        mma16816(d, al[mi], bh[njl], bh[njl+2]);   // al*bh
                    }
                }
            }
        }
        __syncthreads();
    }

    // ---- epilogue ----
    #pragma unroll
    for (int mi=0;mi<2;mi++){
        const int r0 = m0 + wm*32 + mi*16 + (lane>>2);
        #pragma unroll
        for (int nj=0;nj<4;nj++){
            const int c = n0 + wn*32 + nj*8 + (lane&3)*2;
            const float b0 = bias[c], b1 = bias[c+1];
            #pragma unroll
            for (int half=0; half<2; half++){
                const int row = r0 + half*8;
                float v0 = acc[mi][nj][half*2+0] + b0;
                float v1 = acc[mi][nj][half*2+1] + b1;
                if (EPI == 0){
                    const int qi   = c / CDIM;
                    const int rem  = c - qi*CDIM;
                    const int head = rem / HD, hd = rem - head*HD;
                    const int win  = row >> 6, tok = row & 63;
                    const size_t dst = (((size_t)win*HEADS + head)*NTOK + tok)*HD + hd;
                    if (qi==0){      o0[dst] = v0*QSCALE; o0[dst+1] = v1*QSCALE; }
                    else if (qi==1){ o1[dst] = v0;        o1[dst+1] = v1; }
                    else{            o2[dst] = v0;        o2[dst+1] = v1; }
                } else if (EPI == 1){
                    const size_t idx = (size_t)row*Ncols + c;
                    o0[idx]   = v0;
                    o0[idx+1] = v1;
                } else if (EPI == 2){
                    const size_t idx = (size_t)row*Ncols + c;
                    o0[idx]   = 0.5f*v0*(1.f + erff(v0*0.70710678118654752f));
                    o0[idx+1] = 0.5f*v1*(1.f + erff(v1*0.70710678118654752f));
                } else {
                    const size_t idx = (size_t)row*Ncols + c;
                    o0[idx]   = res[idx]   + v0;
                    o0[idx+1] = res[idx+1] + v1;
                }
            }
        }
    }
}

// ============ kernel 3: windowed attention, one block per (window, head) ============
__global__ void __launch_bounds__(64) attn_kernel(const float* __restrict__ rpb)
{
    __shared__ float sk[NTOK*HD];
    __shared__ float sv[NTOK*HD];
    __shared__ float srp[225];
    __shared__ float Ss[NTOK*64];
    const int blk = blockIdx.x;
    const int win = blk >> 3, head = blk & 7;
    const int tid = threadIdx.x;
    const size_t base = (size_t)blk * (NTOK*HD);
    for (int i=tid;i<NTOK*HD;i+=64){ sk[i]=g_k[base+i]; sv[i]=g_v[base+i]; }
    for (int i=tid;i<225;i+=64) srp[i] = rpb[(size_t)i*HEADS + head];

    float qreg[24];
    {
        const float4* qp = reinterpret_cast<const float4*>(&g_q[base + (size_t)tid*HD]);
        #pragma unroll
        for (int i=0;i<6;i++){
            float4 t = qp[i];
            qreg[4*i]=t.x; qreg[4*i+1]=t.y; qreg[4*i+2]=t.z; qreg[4*i+3]=t.w;
        }
    }
    __syncthreads();

    const int wrow = (win & (NW-1)) >> 5;
    const int wcol = win & 31;
    const int r1 = tid >> 3, c1 = tid & 7;

    float mx = -1e30f;
    #pragma unroll 4
    for (int m=0;m<NTOK;m++){
        float s = 0.f;
        #pragma unroll
        for (int d=0;d<24;d++) s += qreg[d]*sk[m*24+d];
        const int r2 = m>>3, c2 = m&7;
        s += srp[(r1-r2+7)*15 + (c1-c2+7)];
        const bool masked = (wrow==31 && ((r1>>2)!=(r2>>2))) ||
                            (wcol==31 && ((c1>>2)!=(c2>>2)));
        if (masked) s -= 100.f;
        Ss[m*64+tid] = s;
        mx = fmaxf(mx, s);
    }
    float sum = 0.f;
    #pragma unroll 4
    for (int m=0;m<NTOK;m++){
        float e = __expf(Ss[m*64+tid] - mx);
        Ss[m*64+tid] = e;
        sum += e;
    }
    const float inv = 1.f/sum;
    float o[24];
    #pragma unroll
    for (int d=0;d<24;d++) o[d]=0.f;
    #pragma unroll 4
    for (int m=0;m<NTOK;m++){
        const float p = Ss[m*64+tid]*inv;
        #pragma unroll
        for (int d=0;d<24;d++) o[d] += p*sv[m*24+d];
    }
    float* op = &g_att[((size_t)win*NTOK + tid)*CDIM + head*HD];
    #pragma unroll
    for (int i=0;i<6;i++)
        reinterpret_cast<float4*>(op)[i] = make_float4(o[4*i],o[4*i+1],o[4*i+2],o[4*i+3]);
}

// ============ kernel 5: window reverse + roll(+4,+4) + residual + LN2 ============
__global__ void __launch_bounds__(128) postattn_kernel(
    const float* __restrict__ x, const float* __restrict__ g, const float* __restrict__ b)
{
    extern __shared__ float s[];
    float* sg = s + CDIM*128;
    float* sb = sg + CDIM;
    const int tid = threadIdx.x;
    const int w0 = blockIdx.x*128, h = blockIdx.y, bb = blockIdx.z;
    for (int i=tid;i<CDIM;i+=128){ sg[i]=g[i]; sb[i]=b[i]; }
    const float* xp = x + (size_t)bb*CDIM*HIMG*WIMG + (size_t)h*WIMG + w0;
    #pragma unroll 4
    for (int c=0;c<CDIM;c++) s[c*128+tid] = xp[(size_t)c*(HIMG*WIMG)+tid];
    __syncthreads();
    const int w  = w0 + tid;
    const int hr = (h-4)&255, wr = (w-4)&255;
    const int win = bb*NW + (hr>>3)*NWX + (wr>>3);
    const size_t pbase = ((size_t)win*NTOK + ((hr&7)<<3) + (wr&7))*CDIM;
    float sum=0.f, sq=0.f;
    for (int c=0;c<CDIM;c++){
        float v = s[c*128+tid] + g_proj[pbase+c];
        s[c*128+tid] = v; sum += v; sq += v*v;
    }
    const float mean = sum*(1.f/CDIM);
    const float var  = sq*(1.f/CDIM) - mean*mean;
    const float rstd = rsqrtf(var + LN_EPS);
    const size_t ob = (((size_t)bb*HIMG + h)*WIMG + w)*CDIM;
    for (int c=0;c<CDIM;c++){
        float v = s[c*128+tid];
        g_xh[ob+c] = v;
        g_h2[ob+c] = (v-mean)*rstd*sg[c] + sb[c];
    }
}

// ============ kernel 8: BHWC -> BCHW output transpose ============
__global__ void out_transpose_kernel(float* __restrict__ out)
{
    __shared__ float t[32][33];
    const int tx = threadIdx.x, ty = threadIdx.y;   // (32, 8)
    const int w0 = blockIdx.x*32, h = blockIdx.y, bb = blockIdx.z;
    const size_t trow = ((size_t)bb*HIMG + h)*WIMG + w0;
    for (int c0=0;c0<CDIM;c0+=32){
        #pragma unroll
        for (int j=0;j<4;j++){
            int wl = ty + j*8;
            t[wl][tx] = g_y[(trow+wl)*CDIM + c0 + tx];
        }
        __syncthreads();
        #pragma unroll
        for (int j=0;j<4;j++){
            int cl = ty + j*8;
            out[(((size_t)bb*CDIM + c0+cl)*HIMG + h)*WIMG + w0 + tx] = t[tx][cl];
        }
        __syncthreads();
    }
}

// ============ launch ============
extern "C" void kernel_launch(void* const* d_in, const int* in_sizes, int n_in,
                              void* d_out, int out_size)
{
    (void)in_sizes; (void)n_in; (void)out_size;
    const float* x      = (const float*)d_in[0];
    const float* n1g    = (const float*)d_in[1];
    const float* n1b    = (const float*)d_in[2];
    const float* qkv_w  = (const float*)d_in[3];
    const float* qkv_b  = (const float*)d_in[4];
    const float* proj_w = (const float*)d_in[5];
    const float* proj_b = (const float*)d_in[6];
    const float* rpb    = (const float*)d_in[7];
    const float* n2g    = (const float*)d_in[8];
    const float* n2b    = (const float*)d_in[9];
    const float* fc1_w  = (const float*)d_in[10];
    const float* fc1_b  = (const float*)d_in[11];
    const float* fc2_w  = (const float*)d_in[12];
    const float* fc2_b  = (const float*)d_in[13];
    float* out = (float*)d_out;

    float *hwin,*q,*k,*v,*att,*proj,*xh,*h2,*mid,*y;
    cudaGetSymbolAddress((void**)&hwin, g_hwin);
    cudaGetSymbolAddress((void**)&q,    g_q);
    cudaGetSymbolAddress((void**)&k,    g_k);
    cudaGetSymbolAddress((void**)&v,    g_v);
    cudaGetSymbolAddress((void**)&att,  g_att);
    cudaGetSymbolAddress((void**)&proj, g_proj);
    cudaGetSymbolAddress((void**)&xh,   g_xh);
    cudaGetSymbolAddress((void**)&h2,   g_h2);
    cudaGetSymbolAddress((void**)&mid,  g_mid);
    cudaGetSymbolAddress((void**)&y,    g_y);

    cudaFuncSetAttribute(ln1_partition_kernel,
        cudaFuncAttributeMaxDynamicSharedMemorySize, LN_SMEM_BYTES);
    cudaFuncSetAttribute(postattn_kernel,
        cudaFuncAttributeMaxDynamicSharedMemorySize, LN_SMEM_BYTES);
    cudaFuncSetAttribute(mma_gemm<0>,
        cudaFuncAttributeMaxDynamicSharedMemorySize, SMEM_MMA);
    cudaFuncSetAttribute(mma_gemm<1>,
        cudaFuncAttributeMaxDynamicSharedMemorySize, SMEM_MMA);
    cudaFuncSetAttribute(mma_gemm<2>,
        cudaFuncAttributeMaxDynamicSharedMemorySize, SMEM_MMA);
    cudaFuncSetAttribute(mma_gemm<3>,
        cudaFuncAttributeMaxDynamicSharedMemorySize, SMEM_MMA);

    const dim3 lnGrid(WIMG/128, HIMG, BATCH);

    // 1. LN1 + roll + window partition
    ln1_partition_kernel<<<lnGrid, 128, LN_SMEM_BYTES>>>(x, n1g, n1b);

    // 2. qkv GEMM (262144 x 192) @ (192 x 576), split q/k/v, q pre-scaled
    mma_gemm<0><<<dim3(9, TPIX/128), 256, SMEM_MMA>>>(
        hwin, qkv_w, qkv_b, q, k, v, nullptr, CDIM, 3*CDIM);

    // 3. attention per (window, head)
    attn_kernel<<<BWIN*HEADS, 64>>>(rpb);

    // 4. proj GEMM (262144 x 192) @ (192 x 192)
    mma_gemm<1><<<dim3(3, TPIX/128), 256, SMEM_MMA>>>(
        att, proj_w, proj_b, proj, nullptr, nullptr, nullptr, CDIM, CDIM);

    // 5. window reverse + roll + residual + LN2
    postattn_kernel<<<lnGrid, 128, LN_SMEM_BYTES>>>(x, n2g, n2b);

    // 6. fc1 GEMM (262144 x 192) @ (192 x 768) + GELU
    mma_gemm<2><<<dim3(12, TPIX/128), 256, SMEM_MMA>>>(
        h2, fc1_w, fc1_b, mid, nullptr, nullptr, nullptr, CDIM, CMID);

    // 7. fc2 GEMM (262144 x 768) @ (768 x 192) + residual
    mma_gemm<3><<<dim3(3, TPIX/128), 256, SMEM_MMA>>>(
        mid, fc2_w, fc2_b, y, nullptr, nullptr, xh, CMID, CDIM);

    // 8. BHWC -> BCHW
    out_transpose_kernel<<<dim3(WIMG/32, HIMG, BATCH), dim3(32,8)>>>(out);
}